// round 14
// baseline (speedup 1.0000x reference)
#include <cuda_runtime.h>
#include <cuda_bf16.h>
#include <cstdint>

#define B_ 128
#define T_ 500
#define D_ 700
#define H_ 512
#define O_ 20
#define K1 704       // GEMM1 K: D padded to 704 (11 stages of 64)
#define K2 512       // GEMM2 K: H (8 stages of 64)
#define SBUF 16384   // one stage buffer: 128 rows x 128 B (SW128 swizzled)
#define STG 3        // cp.async pipeline depth
#define GSMEM (2 * STG * SBUF)   // 98304 bytes dynamic smem
#define ERS 272      // epilogue smem row stride
#define NCH 10       // time chunks
#define CH 50        // T per chunk

// ---------------- scratch (static device globals: no allocation allowed) ----------------
__device__ __nv_bfloat16 g_xc[(size_t)T_ * B_ * K1];   // 90 MB  x as bf16 [t][b][k]
__device__ __nv_bfloat16 g_w1[(size_t)H_ * K1];        // W1 bf16 [h][k]
__device__ __nv_bfloat16 g_w2[(size_t)H_ * K2];        // W2 bf16 [g][h]
__device__ __nv_bfloat16 g_cur[(size_t)T_ * B_ * H_];  // 65 MB  cur1 then cur2 [t][b][h]
__device__ __nv_bfloat16 g_s1[(size_t)T_ * B_ * H_];   // 65 MB  s1 dense bf16 [t][b][h]
__device__ float         g_v1[B_ * H_];                // scan1 membrane state
__device__ float         g_v2[B_ * H_];                // scan2 membrane state
__device__ float         g_S2[B_ * H_];                // running spike counts (layer 2)

// ---------------- helpers ----------------
__device__ __forceinline__ uint32_t smem_u32(const void* p) {
    uint32_t a;
    asm("{ .reg .u64 t; cvta.to.shared.u64 t, %1; cvt.u32.u64 %0, t; }" : "=r"(a) : "l"(p));
    return a;
}
__device__ __forceinline__ void cp16(uint32_t s, const void* g) {
    asm volatile("cp.async.cg.shared.global [%0], [%1], 16;" :: "r"(s), "l"(g));
}
__device__ __forceinline__ void ldsm4(uint32_t& r0, uint32_t& r1, uint32_t& r2,
                                      uint32_t& r3, uint32_t addr) {
    asm volatile("ldmatrix.sync.aligned.m8n8.x4.shared.b16 {%0,%1,%2,%3}, [%4];"
                 : "=r"(r0), "=r"(r1), "=r"(r2), "=r"(r3) : "r"(addr));
}
__device__ __forceinline__ void mma16816(float* c, const uint32_t* a, const uint32_t* b) {
    asm volatile(
        "mma.sync.aligned.m16n8k16.row.col.f32.bf16.bf16.f32 "
        "{%0,%1,%2,%3}, {%4,%5,%6,%7}, {%8,%9}, {%0,%1,%2,%3};"
        : "+f"(c[0]), "+f"(c[1]), "+f"(c[2]), "+f"(c[3])
        : "r"(a[0]), "r"(a[1]), "r"(a[2]), "r"(a[3]), "r"(b[0]), "r"(b[1]));
}
__device__ __forceinline__ uint32_t sw128(uint32_t off) {   // SW128: bits[9:7] ^-> [6:4]
    return off ^ ((off >> 3) & 0x70u);
}

// ---------------- prep: fp32 -> bf16, one time-chunk per launch ----------------
// grid 4400 x 256: exactly CH*B_*176 8B-chunks.
__global__ __launch_bounds__(256) void prep_x_chunk(const float* __restrict__ x, int t0) {
    const int c = blockIdx.x * 256 + threadIdx.x;
    const int tb = c / 176, i = c - tb * 176;
    const int tl = tb / B_, b = tb - tl * B_;
    const int t = t0 + tl;
    const float* xr = x + ((size_t)b * T_ + t) * D_;   // x is [B][T][D]
    __nv_bfloat16* o = g_xc + ((size_t)t * B_ + b) * K1;
    if (i < 175) {
        float4 v = ((const float4*)xr)[i];
        __nv_bfloat162 p0 = __floats2bfloat162_rn(v.x, v.y);
        __nv_bfloat162 p1 = __floats2bfloat162_rn(v.z, v.w);
        uint2 u;
        u.x = *(uint32_t*)&p0;
        u.y = *(uint32_t*)&p1;
        *(uint2*)(o + 4 * i) = u;
    } else {
        *(uint2*)(o + 700) = make_uint2(0u, 0u);       // pad 700..703
    }
}
__global__ void prep_w1(const float* __restrict__ W1) {
    const int h = blockIdx.x;
    const float* wr = W1 + (size_t)h * D_;
    __nv_bfloat16* o = g_w1 + (size_t)h * K1;
    for (int d = threadIdx.x; d < D_; d += 256)
        o[d] = __float2bfloat16(wr[d]);
    if (threadIdx.x < K1 - D_) o[D_ + threadIdx.x] = __float2bfloat16(0.f);
}
__global__ void prep_w2(const float* __restrict__ W2) {
    int i = blockIdx.x * blockDim.x + threadIdx.x;
    if (i < H_ * H_) g_w2[i] = __float2bfloat16(W2[i]);
}

// ---------------- GEMM: out[t*B+m][n] = bf16(A[t*B+m][:].Bm[n][:] + bias[n]) ----------
// grid (4 n-tiles, CH t), 256 threads; t = t0 + blockIdx.y. CTA tile 128x128, K=KK.
// 8 warps as 2(m)x4(n), each 64x32 via m16n8k16. K-stage 64 (SW128), 3-stage ring.
template <int KK>
__global__ __launch_bounds__(256, 2) void gemm_mma(const __nv_bfloat16* __restrict__ Asrc,
                                                   const __nv_bfloat16* __restrict__ Bsrc,
                                                   const float* __restrict__ bias,
                                                   __nv_bfloat16* __restrict__ outp,
                                                   int t0) {
    constexpr int NS = KK / 64;
    constexpr int KB2 = KK * 2;
    extern __shared__ __align__(128) char smem[];
    const int tid = threadIdx.x, lane = tid & 31, wid = tid >> 5;
    const int t = t0 + blockIdx.y, nbase = blockIdx.x * 128;
    const int wm = wid >> 2, wn = wid & 3;

    const char* gA = (const char*)Asrc + (size_t)t * B_ * KB2;
    const char* gB = (const char*)Bsrc + (size_t)nbase * KB2;
    const uint32_t sAu = smem_u32(smem);
    const uint32_t sBu = sAu + STG * SBUF;

    const int lrow = tid >> 1;
    const int lhalf = (tid & 1) * 64;
    const size_t grow = (size_t)lrow * KB2;

    const int arow = lane & 15;
    const int acol = (lane >> 4) * 16;
    const int brow = (lane & 7) + ((lane & 16) ? 8 : 0);
    const int bcol = (lane & 8) ? 16 : 0;

    float acc[4][4][4];
#pragma unroll
    for (int i = 0; i < 4; i++)
#pragma unroll
        for (int j = 0; j < 4; j++)
#pragma unroll
            for (int q = 0; q < 4; q++) acc[i][j][q] = 0.f;

#define LOADSTAGE(s, buf)                                                       \
    do {                                                                        \
        const char* ga = gA + grow + (s) * 128 + lhalf;                         \
        const char* gb = gB + grow + (s) * 128 + lhalf;                         \
        const uint32_t rb = (uint32_t)(lrow * 128 + lhalf);                     \
        _Pragma("unroll")                                                       \
        for (int j = 0; j < 4; j++) {                                           \
            uint32_t sw = sw128(rb + j * 16);                                   \
            cp16(sAu + (buf) * SBUF + sw, ga + j * 16);                         \
            cp16(sBu + (buf) * SBUF + sw, gb + j * 16);                         \
        }                                                                       \
    } while (0)

#pragma unroll
    for (int p = 0; p < STG - 1; p++) {
        LOADSTAGE(p, p);
        asm volatile("cp.async.commit_group;");
    }

    int buf = 0, nbuf = STG - 1;
    for (int s = 0; s < NS; s++) {
        asm volatile("cp.async.wait_group 1;");
        __syncthreads();
        if (s + STG - 1 < NS) LOADSTAGE(s + STG - 1, nbuf);
        asm volatile("cp.async.commit_group;");

        const uint32_t abase = sAu + buf * SBUF;
        const uint32_t bbase = sBu + buf * SBUF;
#pragma unroll
        for (int ks = 0; ks < 4; ks++) {
            uint32_t a[4][4], bf[4][2];
#pragma unroll
            for (int i = 0; i < 4; i++)
                ldsm4(a[i][0], a[i][1], a[i][2], a[i][3],
                      abase + sw128((wm * 64 + i * 16 + arow) * 128 + ks * 32 + acol));
#pragma unroll
            for (int j = 0; j < 2; j++)
                ldsm4(bf[2 * j][0], bf[2 * j][1], bf[2 * j + 1][0], bf[2 * j + 1][1],
                      bbase + sw128((wn * 32 + j * 16 + brow) * 128 + ks * 32 + bcol));
#pragma unroll
            for (int i = 0; i < 4; i++)
#pragma unroll
                for (int j = 0; j < 4; j++) mma16816(acc[i][j], a[i], bf[j]);
        }
        buf = (buf + 1 == STG) ? 0 : buf + 1;
        nbuf = (nbuf + 1 == STG) ? 0 : nbuf + 1;
    }
    __syncthreads();

    const int r0 = wm * 64 + (lane >> 2);
    const int cb = wn * 32 + (lane & 3) * 2;
#pragma unroll
    for (int j = 0; j < 4; j++) {
        const int col = nbase + cb + j * 8;
        const float2 bl = *(const float2*)(bias + col);
#pragma unroll
        for (int i = 0; i < 4; i++) {
            const int rb = r0 + i * 16;
            __nv_bfloat162 v0 = __floats2bfloat162_rn(acc[i][j][0] + bl.x,
                                                      acc[i][j][1] + bl.y);
            __nv_bfloat162 v1 = __floats2bfloat162_rn(acc[i][j][2] + bl.x,
                                                      acc[i][j][3] + bl.y);
            *(uint32_t*)(smem + rb * ERS + (cb + j * 8) * 2)       = *(uint32_t*)&v0;
            *(uint32_t*)(smem + (rb + 8) * ERS + (cb + j * 8) * 2) = *(uint32_t*)&v1;
        }
    }
    __syncthreads();
    char* gOut = (char*)outp + ((size_t)t * B_ * H_ + nbase) * 2;
#pragma unroll
    for (int c = tid; c < 2048; c += 256) {
        const int row = c >> 4, off = (c & 15) * 16;
        uint4 v = *(const uint4*)(smem + row * ERS + off);
        *(uint4*)(gOut + (size_t)row * (H_ * 2) + off) = v;
    }
}

// ---------------- scan1: LIF over cur1 chunk [t0, t0+CH), state in g_v1 ----------------
// grid (2 h-halves, 128 b), 128 threads; thread = one (b, h-pair). No barriers.
__global__ __launch_bounds__(128) void scan1_kernel(int t0) {
    const int q = blockIdx.x, b = blockIdx.y;
    const int tid = threadIdx.x;
    const size_t off2 = (size_t)b * (H_ / 2) + q * 128 + tid;   // bf162 index
    const __nv_bfloat162* cp = (const __nv_bfloat162*)g_cur + off2;
    __nv_bfloat162* sp = (__nv_bfloat162*)g_s1 + off2;
    const int stride = B_ * H_ / 2;
    float v0, v1;
    if (t0 == 0) { v0 = 0.f; v1 = 0.f; }
    else { float2 s = *(float2*)(g_v1 + 2 * off2); v0 = s.x; v1 = s.y; }
    for (int tl = 0; tl < CH; tl += 10) {
        __nv_bfloat162 I[10];
#pragma unroll
        for (int u = 0; u < 10; u++)
            I[u] = cp[(size_t)(t0 + tl + u) * stride];
#pragma unroll
        for (int u = 0; u < 10; u++) {
            float2 f = __bfloat1622float2(I[u]);
            v0 += (f.x - v0) * 0.5f;
            v1 += (f.y - v1) * 0.5f;
            bool s0 = (v0 >= 1.0f), s1v = (v1 >= 1.0f);
            sp[(size_t)(t0 + tl + u) * stride] =
                __floats2bfloat162_rn(s0 ? 1.f : 0.f, s1v ? 1.f : 0.f);
            if (s0) v0 = 0.f;
            if (s1v) v1 = 0.f;
        }
    }
    *(float2*)(g_v1 + 2 * off2) = make_float2(v0, v1);
}

// ---------------- scan2: LIF over cur2 chunk, running counts in g_S2, state g_v2 -------
__global__ __launch_bounds__(128) void scan2_kernel(int t0) {
    const int q = blockIdx.x, b = blockIdx.y;
    const int tid = threadIdx.x;
    const size_t off2 = (size_t)b * (H_ / 2) + q * 128 + tid;
    const __nv_bfloat162* cp = (const __nv_bfloat162*)g_cur + off2;
    const int stride = B_ * H_ / 2;
    float v0, v1, c0, c1;
    if (t0 == 0) { v0 = v1 = c0 = c1 = 0.f; }
    else {
        float2 s = *(float2*)(g_v2 + 2 * off2); v0 = s.x; v1 = s.y;
        float2 c = *(float2*)(g_S2 + 2 * off2); c0 = c.x; c1 = c.y;
    }
    for (int tl = 0; tl < CH; tl += 10) {
        __nv_bfloat162 I[10];
#pragma unroll
        for (int u = 0; u < 10; u++)
            I[u] = cp[(size_t)(t0 + tl + u) * stride];
#pragma unroll
        for (int u = 0; u < 10; u++) {
            float2 f = __bfloat1622float2(I[u]);
            v0 += (f.x - v0) * 0.5f;
            v1 += (f.y - v1) * 0.5f;
            if (v0 >= 1.0f) { v0 = 0.f; c0 += 1.f; }
            if (v1 >= 1.0f) { v1 = 0.f; c1 += 1.f; }
        }
    }
    *(float2*)(g_v2 + 2 * off2) = make_float2(v0, v1);
    *(float2*)(g_S2 + 2 * off2) = make_float2(c0, c1);
}

// ---------------- final: out[b,o] = 500*b3[o] + sum_h S2[b,h] * W3[o,h] ----------------
__global__ void final_kernel(const float* __restrict__ W3, const float* __restrict__ b3,
                             float* __restrict__ out) {
    __shared__ float sW3[O_ * H_];
    __shared__ float part[4 * O_];
    const int b = blockIdx.x, tid = threadIdx.x;
    for (int i = tid; i < O_ * H_; i += 128) sW3[i] = W3[i];
    __syncthreads();

    float acc[O_];
#pragma unroll
    for (int o = 0; o < O_; o++) acc[o] = 0.f;
    for (int h = tid; h < H_; h += 128) {
        float s2 = g_S2[b * H_ + h];
#pragma unroll
        for (int o = 0; o < O_; o++) acc[o] += s2 * sW3[o * H_ + h];
    }
#pragma unroll
    for (int off = 16; off; off >>= 1)
#pragma unroll
        for (int o = 0; o < O_; o++)
            acc[o] += __shfl_down_sync(0xffffffffu, acc[o], off);
    if ((tid & 31) == 0)
#pragma unroll
        for (int o = 0; o < O_; o++) part[(tid >> 5) * O_ + o] = acc[o];
    __syncthreads();
    if (tid < O_) {
        float r = 500.0f * b3[tid];
#pragma unroll
        for (int w = 0; w < 4; w++) r += part[w * O_ + tid];
        out[b * O_ + tid] = r;
    }
}

// ---------------- stream/event context (created once, on the un-captured call) ---------
struct PipeCtx {
    cudaStream_t s1, s2, s3;
    cudaEvent_t eRoot, eW, ePX[NCH], eG1[NCH], eS1[NCH], eG2[NCH], eFin;
    PipeCtx() {
        cudaStreamCreateWithFlags(&s1, cudaStreamNonBlocking);
        cudaStreamCreateWithFlags(&s2, cudaStreamNonBlocking);
        cudaStreamCreateWithFlags(&s3, cudaStreamNonBlocking);
        cudaEventCreateWithFlags(&eRoot, cudaEventDisableTiming);
        cudaEventCreateWithFlags(&eW, cudaEventDisableTiming);
        cudaEventCreateWithFlags(&eFin, cudaEventDisableTiming);
        for (int i = 0; i < NCH; i++) {
            cudaEventCreateWithFlags(&ePX[i], cudaEventDisableTiming);
            cudaEventCreateWithFlags(&eG1[i], cudaEventDisableTiming);
            cudaEventCreateWithFlags(&eS1[i], cudaEventDisableTiming);
            cudaEventCreateWithFlags(&eG2[i], cudaEventDisableTiming);
        }
    }
};

// ---------------- launch: capture-legal 4-stream software pipeline over 10 chunks ------
// s0 (origin): gemm1 chunks + final.  s1: prep_x + scan1 chain.
// s2: gemm2 chunks.                   s3: weight prep + scan2 chain.
extern "C" void kernel_launch(void* const* d_in, const int* in_sizes, int n_in,
                              void* d_out, int out_size) {
    const float* x  = (const float*)d_in[0];   // [128, 500, 700]
    const float* W1 = (const float*)d_in[1];   // [512, 700]
    const float* b1 = (const float*)d_in[2];   // [512]
    const float* W2 = (const float*)d_in[3];   // [512, 512]
    const float* b2 = (const float*)d_in[4];   // [512]
    const float* W3 = (const float*)d_in[5];   // [20, 512]
    const float* b3 = (const float*)d_in[6];   // [20]
    float* out = (float*)d_out;                // [128, 20]

    static PipeCtx P;                          // created on first (eager) call only
    const cudaStream_t s0 = 0;                 // capture-origin stream

    __nv_bfloat16* xc;   cudaGetSymbolAddress((void**)&xc,   g_xc);
    __nv_bfloat16* w1c;  cudaGetSymbolAddress((void**)&w1c,  g_w1);
    __nv_bfloat16* w2c;  cudaGetSymbolAddress((void**)&w2c,  g_w2);
    __nv_bfloat16* s1c;  cudaGetSymbolAddress((void**)&s1c,  g_s1);
    __nv_bfloat16* curc; cudaGetSymbolAddress((void**)&curc, g_cur);

    cudaFuncSetAttribute(gemm_mma<K1>, cudaFuncAttributeMaxDynamicSharedMemorySize, GSMEM);
    cudaFuncSetAttribute(gemm_mma<K2>, cudaFuncAttributeMaxDynamicSharedMemorySize, GSMEM);

    // ---- FORK: all side streams join the capture via an event recorded on s0 ----
    cudaEventRecord(P.eRoot, s0);
    cudaStreamWaitEvent(P.s1, P.eRoot, 0);
    cudaStreamWaitEvent(P.s2, P.eRoot, 0);
    cudaStreamWaitEvent(P.s3, P.eRoot, 0);

    // s3: weight prep (overlaps prep_x chunk 0 on s1)
    prep_w1<<<H_, 256, 0, P.s3>>>(W1);
    prep_w2<<<(H_ * H_ + 255) / 256, 256, 0, P.s3>>>(W2);
    cudaEventRecord(P.eW, P.s3);

    // s1: x chunks
    for (int c = 0; c < NCH; c++) {
        prep_x_chunk<<<4400, 256, 0, P.s1>>>(x, c * CH);
        cudaEventRecord(P.ePX[c], P.s1);
    }

    // s0: gemm1 chunks
    cudaStreamWaitEvent(s0, P.eW, 0);
    for (int c = 0; c < NCH; c++) {
        cudaStreamWaitEvent(s0, P.ePX[c], 0);
        gemm_mma<K1><<<dim3(4, CH), 256, GSMEM, s0>>>(xc, w1c, b1, curc, c * CH);
        cudaEventRecord(P.eG1[c], s0);
    }

    // s1: scan1 chunks (state chain via s1 stream order)
    for (int c = 0; c < NCH; c++) {
        cudaStreamWaitEvent(P.s1, P.eG1[c], 0);
        scan1_kernel<<<dim3(2, B_), 128, 0, P.s1>>>(c * CH);
        cudaEventRecord(P.eS1[c], P.s1);
    }

    // s2: gemm2 chunks (co-run with later gemm1 chunks, filling wave tails)
    cudaStreamWaitEvent(P.s2, P.eW, 0);
    for (int c = 0; c < NCH; c++) {
        cudaStreamWaitEvent(P.s2, P.eS1[c], 0);
        gemm_mma<K2><<<dim3(4, CH), 256, GSMEM, P.s2>>>(s1c, w2c, b2, curc, c * CH);
        cudaEventRecord(P.eG2[c], P.s2);
    }

    // s3: scan2 chunks (state chain via s3 stream order)
    for (int c = 0; c < NCH; c++) {
        cudaStreamWaitEvent(P.s3, P.eG2[c], 0);
        scan2_kernel<<<dim3(2, B_), 128, 0, P.s3>>>(c * CH);
    }
    cudaEventRecord(P.eFin, P.s3);

    // ---- JOIN: every forked stream merges back into s0 before capture ends ----
    cudaStreamWaitEvent(s0, P.eS1[NCH - 1], 0);   // joins s1
    cudaStreamWaitEvent(s0, P.eG2[NCH - 1], 0);   // joins s2
    cudaStreamWaitEvent(s0, P.eFin, 0);           // joins s3
    final_kernel<<<B_, 128, 0, s0>>>(W3, b3, out);
}

// round 15
// speedup vs baseline: 1.0500x; 1.0500x over previous
#include <cuda_runtime.h>
#include <cuda_bf16.h>
#include <cstdint>

#define B_ 128
#define T_ 500
#define D_ 700
#define H_ 512
#define O_ 20
#define K1 704       // GEMM1 K: D padded to 704 (11 stages of 64)
#define K2 512       // GEMM2 K: H (8 stages of 64)
#define SBUF 16384   // one stage buffer: 128 rows x 128 B (SW128 swizzled)
#define STG 3        // cp.async pipeline depth
#define GSMEM (2 * STG * SBUF)   // 98304 bytes dynamic smem
#define ERS 272      // epilogue smem row stride
#define NCH 6        // time chunks (asymmetric: 50,100,100,100,100,50)

static const int CB[NCH + 1] = {0, 50, 150, 250, 350, 450, 500};

// ---------------- scratch (static device globals: no allocation allowed) ----------------
__device__ __nv_bfloat16 g_xc[(size_t)T_ * B_ * K1];   // 90 MB  x as bf16 [t][b][k]
__device__ __nv_bfloat16 g_w1[(size_t)H_ * K1];        // W1 bf16 [h][k]
__device__ __nv_bfloat16 g_w2[(size_t)H_ * K2];        // W2 bf16 [g][h]
__device__ __nv_bfloat16 g_cur[(size_t)T_ * B_ * H_];  // 65 MB  cur1 then cur2 [t][b][h]
__device__ __nv_bfloat16 g_s1[(size_t)T_ * B_ * H_];   // 65 MB  s1 dense bf16 [t][b][h]
__device__ float         g_v1[B_ * H_];                // scan1 membrane state
__device__ float         g_v2[B_ * H_];                // scan2 membrane state
__device__ float         g_S2[B_ * H_];                // running spike counts (layer 2)

// ---------------- helpers ----------------
__device__ __forceinline__ uint32_t smem_u32(const void* p) {
    uint32_t a;
    asm("{ .reg .u64 t; cvta.to.shared.u64 t, %1; cvt.u32.u64 %0, t; }" : "=r"(a) : "l"(p));
    return a;
}
__device__ __forceinline__ void cp16(uint32_t s, const void* g) {
    asm volatile("cp.async.cg.shared.global [%0], [%1], 16;" :: "r"(s), "l"(g));
}
__device__ __forceinline__ void ldsm4(uint32_t& r0, uint32_t& r1, uint32_t& r2,
                                      uint32_t& r3, uint32_t addr) {
    asm volatile("ldmatrix.sync.aligned.m8n8.x4.shared.b16 {%0,%1,%2,%3}, [%4];"
                 : "=r"(r0), "=r"(r1), "=r"(r2), "=r"(r3) : "r"(addr));
}
__device__ __forceinline__ void mma16816(float* c, const uint32_t* a, const uint32_t* b) {
    asm volatile(
        "mma.sync.aligned.m16n8k16.row.col.f32.bf16.bf16.f32 "
        "{%0,%1,%2,%3}, {%4,%5,%6,%7}, {%8,%9}, {%0,%1,%2,%3};"
        : "+f"(c[0]), "+f"(c[1]), "+f"(c[2]), "+f"(c[3])
        : "r"(a[0]), "r"(a[1]), "r"(a[2]), "r"(a[3]), "r"(b[0]), "r"(b[1]));
}
__device__ __forceinline__ uint32_t sw128(uint32_t off) {   // SW128: bits[9:7] ^-> [6:4]
    return off ^ ((off >> 3) & 0x70u);
}

// ---------------- prep: fp32 -> bf16, one time-chunk per launch ----------------
// grid len*88 x 256: exactly len*B_*176 8B-chunks.
__global__ __launch_bounds__(256) void prep_x_chunk(const float* __restrict__ x, int t0) {
    const int c = blockIdx.x * 256 + threadIdx.x;
    const int tb = c / 176, i = c - tb * 176;
    const int tl = tb / B_, b = tb - tl * B_;
    const int t = t0 + tl;
    const float* xr = x + ((size_t)b * T_ + t) * D_;   // x is [B][T][D]
    __nv_bfloat16* o = g_xc + ((size_t)t * B_ + b) * K1;
    if (i < 175) {
        float4 v = ((const float4*)xr)[i];
        __nv_bfloat162 p0 = __floats2bfloat162_rn(v.x, v.y);
        __nv_bfloat162 p1 = __floats2bfloat162_rn(v.z, v.w);
        uint2 u;
        u.x = *(uint32_t*)&p0;
        u.y = *(uint32_t*)&p1;
        *(uint2*)(o + 4 * i) = u;
    } else {
        *(uint2*)(o + 700) = make_uint2(0u, 0u);       // pad 700..703
    }
}
__global__ void prep_w1(const float* __restrict__ W1) {
    const int h = blockIdx.x;
    const float* wr = W1 + (size_t)h * D_;
    __nv_bfloat16* o = g_w1 + (size_t)h * K1;
    for (int d = threadIdx.x; d < D_; d += 256)
        o[d] = __float2bfloat16(wr[d]);
    if (threadIdx.x < K1 - D_) o[D_ + threadIdx.x] = __float2bfloat16(0.f);
}
__global__ void prep_w2(const float* __restrict__ W2) {
    int i = blockIdx.x * blockDim.x + threadIdx.x;
    if (i < H_ * H_) g_w2[i] = __float2bfloat16(W2[i]);
}

// ---------------- GEMM: out[t*B+m][n] = bf16(A[t*B+m][:].Bm[n][:] + bias[n]) ----------
// grid (4 n-tiles, len t), 256 threads; t = t0 + blockIdx.y. CTA tile 128x128, K=KK.
// 8 warps as 2(m)x4(n), each 64x32 via m16n8k16. K-stage 64 (SW128), 3-stage ring.
template <int KK>
__global__ __launch_bounds__(256, 2) void gemm_mma(const __nv_bfloat16* __restrict__ Asrc,
                                                   const __nv_bfloat16* __restrict__ Bsrc,
                                                   const float* __restrict__ bias,
                                                   __nv_bfloat16* __restrict__ outp,
                                                   int t0) {
    constexpr int NS = KK / 64;
    constexpr int KB2 = KK * 2;
    extern __shared__ __align__(128) char smem[];
    const int tid = threadIdx.x, lane = tid & 31, wid = tid >> 5;
    const int t = t0 + blockIdx.y, nbase = blockIdx.x * 128;
    const int wm = wid >> 2, wn = wid & 3;

    const char* gA = (const char*)Asrc + (size_t)t * B_ * KB2;
    const char* gB = (const char*)Bsrc + (size_t)nbase * KB2;
    const uint32_t sAu = smem_u32(smem);
    const uint32_t sBu = sAu + STG * SBUF;

    const int lrow = tid >> 1;
    const int lhalf = (tid & 1) * 64;
    const size_t grow = (size_t)lrow * KB2;

    const int arow = lane & 15;
    const int acol = (lane >> 4) * 16;
    const int brow = (lane & 7) + ((lane & 16) ? 8 : 0);
    const int bcol = (lane & 8) ? 16 : 0;

    float acc[4][4][4];
#pragma unroll
    for (int i = 0; i < 4; i++)
#pragma unroll
        for (int j = 0; j < 4; j++)
#pragma unroll
            for (int q = 0; q < 4; q++) acc[i][j][q] = 0.f;

#define LOADSTAGE(s, buf)                                                       \
    do {                                                                        \
        const char* ga = gA + grow + (s) * 128 + lhalf;                         \
        const char* gb = gB + grow + (s) * 128 + lhalf;                         \
        const uint32_t rb = (uint32_t)(lrow * 128 + lhalf);                     \
        _Pragma("unroll")                                                       \
        for (int j = 0; j < 4; j++) {                                           \
            uint32_t sw = sw128(rb + j * 16);                                   \
            cp16(sAu + (buf) * SBUF + sw, ga + j * 16);                         \
            cp16(sBu + (buf) * SBUF + sw, gb + j * 16);                         \
        }                                                                       \
    } while (0)

#pragma unroll
    for (int p = 0; p < STG - 1; p++) {
        LOADSTAGE(p, p);
        asm volatile("cp.async.commit_group;");
    }

    int buf = 0, nbuf = STG - 1;
    for (int s = 0; s < NS; s++) {
        asm volatile("cp.async.wait_group 1;");
        __syncthreads();
        if (s + STG - 1 < NS) LOADSTAGE(s + STG - 1, nbuf);
        asm volatile("cp.async.commit_group;");

        const uint32_t abase = sAu + buf * SBUF;
        const uint32_t bbase = sBu + buf * SBUF;
#pragma unroll
        for (int ks = 0; ks < 4; ks++) {
            uint32_t a[4][4], bf[4][2];
#pragma unroll
            for (int i = 0; i < 4; i++)
                ldsm4(a[i][0], a[i][1], a[i][2], a[i][3],
                      abase + sw128((wm * 64 + i * 16 + arow) * 128 + ks * 32 + acol));
#pragma unroll
            for (int j = 0; j < 2; j++)
                ldsm4(bf[2 * j][0], bf[2 * j][1], bf[2 * j + 1][0], bf[2 * j + 1][1],
                      bbase + sw128((wn * 32 + j * 16 + brow) * 128 + ks * 32 + bcol));
#pragma unroll
            for (int i = 0; i < 4; i++)
#pragma unroll
                for (int j = 0; j < 4; j++) mma16816(acc[i][j], a[i], bf[j]);
        }
        buf = (buf + 1 == STG) ? 0 : buf + 1;
        nbuf = (nbuf + 1 == STG) ? 0 : nbuf + 1;
    }
    __syncthreads();

    const int r0 = wm * 64 + (lane >> 2);
    const int cb = wn * 32 + (lane & 3) * 2;
#pragma unroll
    for (int j = 0; j < 4; j++) {
        const int col = nbase + cb + j * 8;
        const float2 bl = *(const float2*)(bias + col);
#pragma unroll
        for (int i = 0; i < 4; i++) {
            const int rb = r0 + i * 16;
            __nv_bfloat162 v0 = __floats2bfloat162_rn(acc[i][j][0] + bl.x,
                                                      acc[i][j][1] + bl.y);
            __nv_bfloat162 v1 = __floats2bfloat162_rn(acc[i][j][2] + bl.x,
                                                      acc[i][j][3] + bl.y);
            *(uint32_t*)(smem + rb * ERS + (cb + j * 8) * 2)       = *(uint32_t*)&v0;
            *(uint32_t*)(smem + (rb + 8) * ERS + (cb + j * 8) * 2) = *(uint32_t*)&v1;
        }
    }
    __syncthreads();
    char* gOut = (char*)outp + ((size_t)t * B_ * H_ + nbase) * 2;
#pragma unroll
    for (int c = tid; c < 2048; c += 256) {
        const int row = c >> 4, off = (c & 15) * 16;
        uint4 v = *(const uint4*)(smem + row * ERS + off);
        *(uint4*)(gOut + (size_t)row * (H_ * 2) + off) = v;
    }
}

// ---------------- scan1: LIF over cur1 chunk [t0, t0+len), state in g_v1 ---------------
// grid (2 h-halves, 128 b), 128 threads; thread = one (b, h-pair). No barriers.
__global__ __launch_bounds__(128) void scan1_kernel(int t0, int len) {
    const int q = blockIdx.x, b = blockIdx.y;
    const int tid = threadIdx.x;
    const size_t off2 = (size_t)b * (H_ / 2) + q * 128 + tid;   // bf162 index
    const __nv_bfloat162* cp = (const __nv_bfloat162*)g_cur + off2;
    __nv_bfloat162* sp = (__nv_bfloat162*)g_s1 + off2;
    const int stride = B_ * H_ / 2;
    float v0, v1;
    if (t0 == 0) { v0 = 0.f; v1 = 0.f; }
    else { float2 s = *(float2*)(g_v1 + 2 * off2); v0 = s.x; v1 = s.y; }
    for (int tl = 0; tl < len; tl += 10) {
        __nv_bfloat162 I[10];
#pragma unroll
        for (int u = 0; u < 10; u++)
            I[u] = cp[(size_t)(t0 + tl + u) * stride];
#pragma unroll
        for (int u = 0; u < 10; u++) {
            float2 f = __bfloat1622float2(I[u]);
            v0 += (f.x - v0) * 0.5f;
            v1 += (f.y - v1) * 0.5f;
            bool s0 = (v0 >= 1.0f), s1v = (v1 >= 1.0f);
            sp[(size_t)(t0 + tl + u) * stride] =
                __floats2bfloat162_rn(s0 ? 1.f : 0.f, s1v ? 1.f : 0.f);
            if (s0) v0 = 0.f;
            if (s1v) v1 = 0.f;
        }
    }
    *(float2*)(g_v1 + 2 * off2) = make_float2(v0, v1);
}

// ---------------- scan2: LIF over cur2 chunk, running counts in g_S2, state g_v2 -------
__global__ __launch_bounds__(128) void scan2_kernel(int t0, int len) {
    const int q = blockIdx.x, b = blockIdx.y;
    const int tid = threadIdx.x;
    const size_t off2 = (size_t)b * (H_ / 2) + q * 128 + tid;
    const __nv_bfloat162* cp = (const __nv_bfloat162*)g_cur + off2;
    const int stride = B_ * H_ / 2;
    float v0, v1, c0, c1;
    if (t0 == 0) { v0 = v1 = c0 = c1 = 0.f; }
    else {
        float2 s = *(float2*)(g_v2 + 2 * off2); v0 = s.x; v1 = s.y;
        float2 c = *(float2*)(g_S2 + 2 * off2); c0 = c.x; c1 = c.y;
    }
    for (int tl = 0; tl < len; tl += 10) {
        __nv_bfloat162 I[10];
#pragma unroll
        for (int u = 0; u < 10; u++)
            I[u] = cp[(size_t)(t0 + tl + u) * stride];
#pragma unroll
        for (int u = 0; u < 10; u++) {
            float2 f = __bfloat1622float2(I[u]);
            v0 += (f.x - v0) * 0.5f;
            v1 += (f.y - v1) * 0.5f;
            if (v0 >= 1.0f) { v0 = 0.f; c0 += 1.f; }
            if (v1 >= 1.0f) { v1 = 0.f; c1 += 1.f; }
        }
    }
    *(float2*)(g_v2 + 2 * off2) = make_float2(v0, v1);
    *(float2*)(g_S2 + 2 * off2) = make_float2(c0, c1);
}

// ---------------- final: out[b,o] = 500*b3[o] + sum_h S2[b,h] * W3[o,h] ----------------
__global__ void final_kernel(const float* __restrict__ W3, const float* __restrict__ b3,
                             float* __restrict__ out) {
    __shared__ float sW3[O_ * H_];
    __shared__ float part[4 * O_];
    const int b = blockIdx.x, tid = threadIdx.x;
    for (int i = tid; i < O_ * H_; i += 128) sW3[i] = W3[i];
    __syncthreads();

    float acc[O_];
#pragma unroll
    for (int o = 0; o < O_; o++) acc[o] = 0.f;
    for (int h = tid; h < H_; h += 128) {
        float s2 = g_S2[b * H_ + h];
#pragma unroll
        for (int o = 0; o < O_; o++) acc[o] += s2 * sW3[o * H_ + h];
    }
#pragma unroll
    for (int off = 16; off; off >>= 1)
#pragma unroll
        for (int o = 0; o < O_; o++)
            acc[o] += __shfl_down_sync(0xffffffffu, acc[o], off);
    if ((tid & 31) == 0)
#pragma unroll
        for (int o = 0; o < O_; o++) part[(tid >> 5) * O_ + o] = acc[o];
    __syncthreads();
    if (tid < O_) {
        float r = 500.0f * b3[tid];
#pragma unroll
        for (int w = 0; w < 4; w++) r += part[w * O_ + tid];
        out[b * O_ + tid] = r;
    }
}

// ---------------- stream/event context (created once, on the un-captured call) ---------
struct PipeCtx {
    cudaStream_t s1, s2, s3;
    cudaEvent_t eRoot, eW, ePX[NCH], eG1[NCH], eS1[NCH], eG2[NCH], eFin;
    PipeCtx() {
        cudaStreamCreateWithFlags(&s1, cudaStreamNonBlocking);
        cudaStreamCreateWithFlags(&s2, cudaStreamNonBlocking);
        cudaStreamCreateWithFlags(&s3, cudaStreamNonBlocking);
        cudaEventCreateWithFlags(&eRoot, cudaEventDisableTiming);
        cudaEventCreateWithFlags(&eW, cudaEventDisableTiming);
        cudaEventCreateWithFlags(&eFin, cudaEventDisableTiming);
        for (int i = 0; i < NCH; i++) {
            cudaEventCreateWithFlags(&ePX[i], cudaEventDisableTiming);
            cudaEventCreateWithFlags(&eG1[i], cudaEventDisableTiming);
            cudaEventCreateWithFlags(&eS1[i], cudaEventDisableTiming);
            cudaEventCreateWithFlags(&eG2[i], cudaEventDisableTiming);
        }
    }
};

// ---------------- launch: 4-stream pipeline, asymmetric chunks 50/100x4/50 -------------
// s0 (origin): gemm1 chunks + final.  s1: prep_x + scan1 chain.
// s2: gemm2 chunks.                   s3: weight prep + scan2 chain.
extern "C" void kernel_launch(void* const* d_in, const int* in_sizes, int n_in,
                              void* d_out, int out_size) {
    const float* x  = (const float*)d_in[0];   // [128, 500, 700]
    const float* W1 = (const float*)d_in[1];   // [512, 700]
    const float* b1 = (const float*)d_in[2];   // [512]
    const float* W2 = (const float*)d_in[3];   // [512, 512]
    const float* b2 = (const float*)d_in[4];   // [512]
    const float* W3 = (const float*)d_in[5];   // [20, 512]
    const float* b3 = (const float*)d_in[6];   // [20]
    float* out = (float*)d_out;                // [128, 20]

    static PipeCtx P;                          // created on first (eager) call only
    const cudaStream_t s0 = 0;                 // capture-origin stream

    __nv_bfloat16* xc;   cudaGetSymbolAddress((void**)&xc,   g_xc);
    __nv_bfloat16* w1c;  cudaGetSymbolAddress((void**)&w1c,  g_w1);
    __nv_bfloat16* w2c;  cudaGetSymbolAddress((void**)&w2c,  g_w2);
    __nv_bfloat16* s1c;  cudaGetSymbolAddress((void**)&s1c,  g_s1);
    __nv_bfloat16* curc; cudaGetSymbolAddress((void**)&curc, g_cur);

    cudaFuncSetAttribute(gemm_mma<K1>, cudaFuncAttributeMaxDynamicSharedMemorySize, GSMEM);
    cudaFuncSetAttribute(gemm_mma<K2>, cudaFuncAttributeMaxDynamicSharedMemorySize, GSMEM);

    // ---- FORK: all side streams join the capture via an event recorded on s0 ----
    cudaEventRecord(P.eRoot, s0);
    cudaStreamWaitEvent(P.s1, P.eRoot, 0);
    cudaStreamWaitEvent(P.s2, P.eRoot, 0);
    cudaStreamWaitEvent(P.s3, P.eRoot, 0);

    // s3: weight prep (overlaps prep_x chunk 0 on s1)
    prep_w1<<<H_, 256, 0, P.s3>>>(W1);
    prep_w2<<<(H_ * H_ + 255) / 256, 256, 0, P.s3>>>(W2);
    cudaEventRecord(P.eW, P.s3);

    // s1: x chunks
    for (int c = 0; c < NCH; c++) {
        const int t0 = CB[c], len = CB[c + 1] - CB[c];
        prep_x_chunk<<<len * 88, 256, 0, P.s1>>>(x, t0);
        cudaEventRecord(P.ePX[c], P.s1);
    }

    // s0: gemm1 chunks
    cudaStreamWaitEvent(s0, P.eW, 0);
    for (int c = 0; c < NCH; c++) {
        const int t0 = CB[c], len = CB[c + 1] - CB[c];
        cudaStreamWaitEvent(s0, P.ePX[c], 0);
        gemm_mma<K1><<<dim3(4, len), 256, GSMEM, s0>>>(xc, w1c, b1, curc, t0);
        cudaEventRecord(P.eG1[c], s0);
    }

    // s1: scan1 chunks (state chain via s1 stream order)
    for (int c = 0; c < NCH; c++) {
        const int t0 = CB[c], len = CB[c + 1] - CB[c];
        cudaStreamWaitEvent(P.s1, P.eG1[c], 0);
        scan1_kernel<<<dim3(2, B_), 128, 0, P.s1>>>(t0, len);
        cudaEventRecord(P.eS1[c], P.s1);
    }

    // s2: gemm2 chunks (co-run with later gemm1 chunks, filling wave tails)
    cudaStreamWaitEvent(P.s2, P.eW, 0);
    for (int c = 0; c < NCH; c++) {
        const int t0 = CB[c], len = CB[c + 1] - CB[c];
        cudaStreamWaitEvent(P.s2, P.eS1[c], 0);
        gemm_mma<K2><<<dim3(4, len), 256, GSMEM, P.s2>>>(s1c, w2c, b2, curc, t0);
        cudaEventRecord(P.eG2[c], P.s2);
    }

    // s3: scan2 chunks (state chain via s3 stream order)
    for (int c = 0; c < NCH; c++) {
        const int t0 = CB[c], len = CB[c + 1] - CB[c];
        cudaStreamWaitEvent(P.s3, P.eG2[c], 0);
        scan2_kernel<<<dim3(2, B_), 128, 0, P.s3>>>(t0, len);
    }
    cudaEventRecord(P.eFin, P.s3);

    // ---- JOIN: every forked stream merges back into s0 before capture ends ----
    cudaStreamWaitEvent(s0, P.eS1[NCH - 1], 0);   // joins s1
    cudaStreamWaitEvent(s0, P.eG2[NCH - 1], 0);   // joins s2
    cudaStreamWaitEvent(s0, P.eFin, 0);           // joins s3
    final_kernel<<<B_, 128, 0, s0>>>(W3, b3, out);
}

// round 17
// speedup vs baseline: 1.0951x; 1.0430x over previous
#include <cuda_runtime.h>
#include <cuda_bf16.h>
#include <cstdint>

#define B_ 128
#define T_ 500
#define D_ 700
#define H_ 512
#define O_ 20
#define K1 704       // GEMM1 K: D padded to 704 (11 stages of 64)
#define K2 512       // GEMM2 K: H (8 stages of 64)
#define SBUF 16384   // one stage buffer: 128 rows x 128 B (SW128 swizzled)
#define STG 3        // cp.async pipeline depth
#define GSMEM (2 * STG * SBUF)   // 98304 bytes dynamic smem
#define ERS 272      // epilogue smem row stride
#define NCH 5        // time chunks
#define CH 100       // T per chunk

// ---------------- scratch (static device globals: no allocation allowed) ----------------
__device__ __nv_bfloat16 g_xc[(size_t)T_ * B_ * K1];   // 90 MB  x as bf16 [t][b][k]
__device__ __nv_bfloat16 g_w1[(size_t)H_ * K1];        // W1 bf16 [h][k]
__device__ __nv_bfloat16 g_w2[(size_t)H_ * K2];        // W2 bf16 [g][h]
__device__ __nv_bfloat16 g_cur[(size_t)T_ * B_ * H_];  // 65 MB  cur1 then cur2 [t][b][h]
__device__ __nv_bfloat16 g_s1[(size_t)T_ * B_ * H_];   // 65 MB  s1 dense bf16 [t][b][h]
__device__ float         g_v1[B_ * H_];                // scan1 membrane state
__device__ float         g_v2[B_ * H_];                // scan2 membrane state
__device__ float         g_S2[B_ * H_];                // running spike counts (layer 2)

// ---------------- helpers ----------------
__device__ __forceinline__ uint32_t smem_u32(const void* p) {
    uint32_t a;
    asm("{ .reg .u64 t; cvta.to.shared.u64 t, %1; cvt.u32.u64 %0, t; }" : "=r"(a) : "l"(p));
    return a;
}
__device__ __forceinline__ void cp16(uint32_t s, const void* g) {
    asm volatile("cp.async.cg.shared.global [%0], [%1], 16;" :: "r"(s), "l"(g));
}
__device__ __forceinline__ void ldsm4(uint32_t& r0, uint32_t& r1, uint32_t& r2,
                                      uint32_t& r3, uint32_t addr) {
    asm volatile("ldmatrix.sync.aligned.m8n8.x4.shared.b16 {%0,%1,%2,%3}, [%4];"
                 : "=r"(r0), "=r"(r1), "=r"(r2), "=r"(r3) : "r"(addr));
}
__device__ __forceinline__ void mma16816(float* c, const uint32_t* a, const uint32_t* b) {
    asm volatile(
        "mma.sync.aligned.m16n8k16.row.col.f32.bf16.bf16.f32 "
        "{%0,%1,%2,%3}, {%4,%5,%6,%7}, {%8,%9}, {%0,%1,%2,%3};"
        : "+f"(c[0]), "+f"(c[1]), "+f"(c[2]), "+f"(c[3])
        : "r"(a[0]), "r"(a[1]), "r"(a[2]), "r"(a[3]), "r"(b[0]), "r"(b[1]));
}
__device__ __forceinline__ uint32_t sw128(uint32_t off) {   // SW128: bits[9:7] ^-> [6:4]
    return off ^ ((off >> 3) & 0x70u);
}

// ---------------- prep: fp32 -> bf16, one time-chunk per launch ----------------
// grid 8800 x 256: exactly CH*B_*176 8B-chunks.
__global__ __launch_bounds__(256) void prep_x_chunk(const float* __restrict__ x, int t0) {
    const int c = blockIdx.x * 256 + threadIdx.x;
    const int tb = c / 176, i = c - tb * 176;
    const int tl = tb / B_, b = tb - tl * B_;
    const int t = t0 + tl;
    const float* xr = x + ((size_t)b * T_ + t) * D_;   // x is [B][T][D]
    __nv_bfloat16* o = g_xc + ((size_t)t * B_ + b) * K1;
    if (i < 175) {
        float4 v = ((const float4*)xr)[i];
        __nv_bfloat162 p0 = __floats2bfloat162_rn(v.x, v.y);
        __nv_bfloat162 p1 = __floats2bfloat162_rn(v.z, v.w);
        uint2 u;
        u.x = *(uint32_t*)&p0;
        u.y = *(uint32_t*)&p1;
        *(uint2*)(o + 4 * i) = u;
    } else {
        *(uint2*)(o + 700) = make_uint2(0u, 0u);       // pad 700..703
    }
}
__global__ void prep_w1(const float* __restrict__ W1) {
    const int h = blockIdx.x;
    const float* wr = W1 + (size_t)h * D_;
    __nv_bfloat16* o = g_w1 + (size_t)h * K1;
    for (int d = threadIdx.x; d < D_; d += 256)
        o[d] = __float2bfloat16(wr[d]);
    if (threadIdx.x < K1 - D_) o[D_ + threadIdx.x] = __float2bfloat16(0.f);
}
__global__ void prep_w2(const float* __restrict__ W2) {
    int i = blockIdx.x * blockDim.x + threadIdx.x;
    if (i < H_ * H_) g_w2[i] = __float2bfloat16(W2[i]);
}

// ---------------- GEMM: out[t*B+m][n] = bf16(A[t*B+m][:].Bm[n][:] + bias[n]) ----------
// grid (4 n-tiles, CH t), 256 threads; t = t0 + blockIdx.y. CTA tile 128x128, K=KK.
// 8 warps as 2(m)x4(n), each 64x32 via m16n8k16. K-stage 64 (SW128), 3-stage ring.
template <int KK>
__global__ __launch_bounds__(256, 2) void gemm_mma(const __nv_bfloat16* __restrict__ Asrc,
                                                   const __nv_bfloat16* __restrict__ Bsrc,
                                                   const float* __restrict__ bias,
                                                   __nv_bfloat16* __restrict__ outp,
                                                   int t0) {
    constexpr int NS = KK / 64;
    constexpr int KB2 = KK * 2;
    extern __shared__ __align__(128) char smem[];
    const int tid = threadIdx.x, lane = tid & 31, wid = tid >> 5;
    const int t = t0 + blockIdx.y, nbase = blockIdx.x * 128;
    const int wm = wid >> 2, wn = wid & 3;

    const char* gA = (const char*)Asrc + (size_t)t * B_ * KB2;
    const char* gB = (const char*)Bsrc + (size_t)nbase * KB2;
    const uint32_t sAu = smem_u32(smem);
    const uint32_t sBu = sAu + STG * SBUF;

    const int lrow = tid >> 1;
    const int lhalf = (tid & 1) * 64;
    const size_t grow = (size_t)lrow * KB2;

    const int arow = lane & 15;
    const int acol = (lane >> 4) * 16;
    const int brow = (lane & 7) + ((lane & 16) ? 8 : 0);
    const int bcol = (lane & 8) ? 16 : 0;

    float acc[4][4][4];
#pragma unroll
    for (int i = 0; i < 4; i++)
#pragma unroll
        for (int j = 0; j < 4; j++)
#pragma unroll
            for (int q = 0; q < 4; q++) acc[i][j][q] = 0.f;

#define LOADSTAGE(s, buf)                                                       \
    do {                                                                        \
        const char* ga = gA + grow + (s) * 128 + lhalf;                         \
        const char* gb = gB + grow + (s) * 128 + lhalf;                         \
        const uint32_t rb = (uint32_t)(lrow * 128 + lhalf);                     \
        _Pragma("unroll")                                                       \
        for (int j = 0; j < 4; j++) {                                           \
            uint32_t sw = sw128(rb + j * 16);                                   \
            cp16(sAu + (buf) * SBUF + sw, ga + j * 16);                         \
            cp16(sBu + (buf) * SBUF + sw, gb + j * 16);                         \
        }                                                                       \
    } while (0)

#pragma unroll
    for (int p = 0; p < STG - 1; p++) {
        LOADSTAGE(p, p);
        asm volatile("cp.async.commit_group;");
    }

    int buf = 0, nbuf = STG - 1;
    for (int s = 0; s < NS; s++) {
        asm volatile("cp.async.wait_group 1;");
        __syncthreads();
        if (s + STG - 1 < NS) LOADSTAGE(s + STG - 1, nbuf);
        asm volatile("cp.async.commit_group;");

        const uint32_t abase = sAu + buf * SBUF;
        const uint32_t bbase = sBu + buf * SBUF;
#pragma unroll
        for (int ks = 0; ks < 4; ks++) {
            uint32_t a[4][4], bf[4][2];
#pragma unroll
            for (int i = 0; i < 4; i++)
                ldsm4(a[i][0], a[i][1], a[i][2], a[i][3],
                      abase + sw128((wm * 64 + i * 16 + arow) * 128 + ks * 32 + acol));
#pragma unroll
            for (int j = 0; j < 2; j++)
                ldsm4(bf[2 * j][0], bf[2 * j][1], bf[2 * j + 1][0], bf[2 * j + 1][1],
                      bbase + sw128((wn * 32 + j * 16 + brow) * 128 + ks * 32 + bcol));
#pragma unroll
            for (int i = 0; i < 4; i++)
#pragma unroll
                for (int j = 0; j < 4; j++) mma16816(acc[i][j], a[i], bf[j]);
        }
        buf = (buf + 1 == STG) ? 0 : buf + 1;
        nbuf = (nbuf + 1 == STG) ? 0 : nbuf + 1;
    }
    __syncthreads();

    const int r0 = wm * 64 + (lane >> 2);
    const int cb = wn * 32 + (lane & 3) * 2;
#pragma unroll
    for (int j = 0; j < 4; j++) {
        const int col = nbase + cb + j * 8;
        const float2 bl = *(const float2*)(bias + col);
#pragma unroll
        for (int i = 0; i < 4; i++) {
            const int rb = r0 + i * 16;
            __nv_bfloat162 v0 = __floats2bfloat162_rn(acc[i][j][0] + bl.x,
                                                      acc[i][j][1] + bl.y);
            __nv_bfloat162 v1 = __floats2bfloat162_rn(acc[i][j][2] + bl.x,
                                                      acc[i][j][3] + bl.y);
            *(uint32_t*)(smem + rb * ERS + (cb + j * 8) * 2)       = *(uint32_t*)&v0;
            *(uint32_t*)(smem + (rb + 8) * ERS + (cb + j * 8) * 2) = *(uint32_t*)&v1;
        }
    }
    __syncthreads();
    char* gOut = (char*)outp + ((size_t)t * B_ * H_ + nbase) * 2;
#pragma unroll
    for (int c = tid; c < 2048; c += 256) {
        const int row = c >> 4, off = (c & 15) * 16;
        uint4 v = *(const uint4*)(smem + row * ERS + off);
        *(uint4*)(gOut + (size_t)row * (H_ * 2) + off) = v;
    }
}

// ---------------- scan1: LIF over cur1 chunk [t0, t0+CH), state in g_v1 ----------------
// grid (2 h-halves, 128 b), 128 threads; thread = one (b, h-pair). No barriers.
__global__ __launch_bounds__(128) void scan1_kernel(int t0) {
    const int q = blockIdx.x, b = blockIdx.y;
    const int tid = threadIdx.x;
    const size_t off2 = (size_t)b * (H_ / 2) + q * 128 + tid;   // bf162 index
    const __nv_bfloat162* cp = (const __nv_bfloat162*)g_cur + off2;
    __nv_bfloat162* sp = (__nv_bfloat162*)g_s1 + off2;
    const int stride = B_ * H_ / 2;
    float v0, v1;
    if (t0 == 0) { v0 = 0.f; v1 = 0.f; }
    else { float2 s = *(float2*)(g_v1 + 2 * off2); v0 = s.x; v1 = s.y; }
    for (int tl = 0; tl < CH; tl += 10) {
        __nv_bfloat162 I[10];
#pragma unroll
        for (int u = 0; u < 10; u++)
            I[u] = cp[(size_t)(t0 + tl + u) * stride];
#pragma unroll
        for (int u = 0; u < 10; u++) {
            float2 f = __bfloat1622float2(I[u]);
            v0 += (f.x - v0) * 0.5f;
            v1 += (f.y - v1) * 0.5f;
            bool s0 = (v0 >= 1.0f), s1v = (v1 >= 1.0f);
            sp[(size_t)(t0 + tl + u) * stride] =
                __floats2bfloat162_rn(s0 ? 1.f : 0.f, s1v ? 1.f : 0.f);
            if (s0) v0 = 0.f;
            if (s1v) v1 = 0.f;
        }
    }
    *(float2*)(g_v1 + 2 * off2) = make_float2(v0, v1);
}

// ---------------- scan2: LIF over cur2 chunk, running counts in g_S2, state g_v2 -------
__global__ __launch_bounds__(128) void scan2_kernel(int t0) {
    const int q = blockIdx.x, b = blockIdx.y;
    const int tid = threadIdx.x;
    const size_t off2 = (size_t)b * (H_ / 2) + q * 128 + tid;
    const __nv_bfloat162* cp = (const __nv_bfloat162*)g_cur + off2;
    const int stride = B_ * H_ / 2;
    float v0, v1, c0, c1;
    if (t0 == 0) { v0 = v1 = c0 = c1 = 0.f; }
    else {
        float2 s = *(float2*)(g_v2 + 2 * off2); v0 = s.x; v1 = s.y;
        float2 c = *(float2*)(g_S2 + 2 * off2); c0 = c.x; c1 = c.y;
    }
    for (int tl = 0; tl < CH; tl += 10) {
        __nv_bfloat162 I[10];
#pragma unroll
        for (int u = 0; u < 10; u++)
            I[u] = cp[(size_t)(t0 + tl + u) * stride];
#pragma unroll
        for (int u = 0; u < 10; u++) {
            float2 f = __bfloat1622float2(I[u]);
            v0 += (f.x - v0) * 0.5f;
            v1 += (f.y - v1) * 0.5f;
            if (v0 >= 1.0f) { v0 = 0.f; c0 += 1.f; }
            if (v1 >= 1.0f) { v1 = 0.f; c1 += 1.f; }
        }
    }
    *(float2*)(g_v2 + 2 * off2) = make_float2(v0, v1);
    *(float2*)(g_S2 + 2 * off2) = make_float2(c0, c1);
}

// ---------------- final: out[b,o] = 500*b3[o] + sum_h S2[b,h] * W3[o,h] ----------------
__global__ void final_kernel(const float* __restrict__ W3, const float* __restrict__ b3,
                             float* __restrict__ out) {
    __shared__ float sW3[O_ * H_];
    __shared__ float part[4 * O_];
    const int b = blockIdx.x, tid = threadIdx.x;
    for (int i = tid; i < O_ * H_; i += 128) sW3[i] = W3[i];
    __syncthreads();

    float acc[O_];
#pragma unroll
    for (int o = 0; o < O_; o++) acc[o] = 0.f;
    for (int h = tid; h < H_; h += 128) {
        float s2 = g_S2[b * H_ + h];
#pragma unroll
        for (int o = 0; o < O_; o++) acc[o] += s2 * sW3[o * H_ + h];
    }
#pragma unroll
    for (int off = 16; off; off >>= 1)
#pragma unroll
        for (int o = 0; o < O_; o++)
            acc[o] += __shfl_down_sync(0xffffffffu, acc[o], off);
    if ((tid & 31) == 0)
#pragma unroll
        for (int o = 0; o < O_; o++) part[(tid >> 5) * O_ + o] = acc[o];
    __syncthreads();
    if (tid < O_) {
        float r = 500.0f * b3[tid];
#pragma unroll
        for (int w = 0; w < 4; w++) r += part[w * O_ + tid];
        out[b * O_ + tid] = r;
    }
}

// ---------------- stream/event context (created once, on the un-captured call) ---------
// Exactly R13's resource footprint (3 streams + 23 events) — proven delta=0 under the
// harness allocation guard. R16's extra streams tripped the 2MB limit.
struct PipeCtx {
    cudaStream_t s1, s2, s3;
    cudaEvent_t eRoot, eW, ePX[NCH], eG1[NCH], eS1[NCH], eG2[NCH], eFin;
    PipeCtx() {
        cudaStreamCreateWithFlags(&s1, cudaStreamNonBlocking);
        cudaStreamCreateWithFlags(&s2, cudaStreamNonBlocking);
        cudaStreamCreateWithFlags(&s3, cudaStreamNonBlocking);
        cudaEventCreateWithFlags(&eRoot, cudaEventDisableTiming);
        cudaEventCreateWithFlags(&eW, cudaEventDisableTiming);
        cudaEventCreateWithFlags(&eFin, cudaEventDisableTiming);
        for (int i = 0; i < NCH; i++) {
            cudaEventCreateWithFlags(&ePX[i], cudaEventDisableTiming);
            cudaEventCreateWithFlags(&eG1[i], cudaEventDisableTiming);
            cudaEventCreateWithFlags(&eS1[i], cudaEventDisableTiming);
            cudaEventCreateWithFlags(&eG2[i], cudaEventDisableTiming);
        }
    }
};

// ---------------- launch: 4-stream pipeline; GEMMs interleave across s0/s2 -------------
// s0: g1c0, g1c2, g1c4, g2c1, g2c3, final.   s2: g1c1, g1c3, g2c0, g2c2, g2c4.
// s1: prep_x + scan1 chain.                  s3: weight prep + scan2 chain.
// Two GEMM lanes from t=0 backfill each chunk's partial tail wave; dataflow edges
// (ePX -> g1, eG1 -> scan1, eS1 -> g2, eG2 -> scan2) identical to the R13 winner.
extern "C" void kernel_launch(void* const* d_in, const int* in_sizes, int n_in,
                              void* d_out, int out_size) {
    const float* x  = (const float*)d_in[0];   // [128, 500, 700]
    const float* W1 = (const float*)d_in[1];   // [512, 700]
    const float* b1 = (const float*)d_in[2];   // [512]
    const float* W2 = (const float*)d_in[3];   // [512, 512]
    const float* b2 = (const float*)d_in[4];   // [512]
    const float* W3 = (const float*)d_in[5];   // [20, 512]
    const float* b3 = (const float*)d_in[6];   // [20]
    float* out = (float*)d_out;                // [128, 20]

    static PipeCtx P;                          // created on first (eager) call only
    const cudaStream_t s0 = 0;                 // capture-origin stream

    __nv_bfloat16* xc;   cudaGetSymbolAddress((void**)&xc,   g_xc);
    __nv_bfloat16* w1c;  cudaGetSymbolAddress((void**)&w1c,  g_w1);
    __nv_bfloat16* w2c;  cudaGetSymbolAddress((void**)&w2c,  g_w2);
    __nv_bfloat16* s1c;  cudaGetSymbolAddress((void**)&s1c,  g_s1);
    __nv_bfloat16* curc; cudaGetSymbolAddress((void**)&curc, g_cur);

    cudaFuncSetAttribute(gemm_mma<K1>, cudaFuncAttributeMaxDynamicSharedMemorySize, GSMEM);
    cudaFuncSetAttribute(gemm_mma<K2>, cudaFuncAttributeMaxDynamicSharedMemorySize, GSMEM);

    // ---- FORK: all side streams join the capture via an event recorded on s0 ----
    cudaEventRecord(P.eRoot, s0);
    cudaStreamWaitEvent(P.s1, P.eRoot, 0);
    cudaStreamWaitEvent(P.s2, P.eRoot, 0);
    cudaStreamWaitEvent(P.s3, P.eRoot, 0);

    // s3: weight prep (overlaps prep_x chunk 0 on s1)
    prep_w1<<<H_, 256, 0, P.s3>>>(W1);
    prep_w2<<<(H_ * H_ + 255) / 256, 256, 0, P.s3>>>(W2);
    cudaEventRecord(P.eW, P.s3);

    // s1: x chunks
    for (int c = 0; c < NCH; c++) {
        prep_x_chunk<<<8800, 256, 0, P.s1>>>(x, c * CH);
        cudaEventRecord(P.ePX[c], P.s1);
    }

    // gemm1 chunks: even -> s0, odd -> s2 (two lanes from the start)
    cudaStreamWaitEvent(s0, P.eW, 0);
    cudaStreamWaitEvent(P.s2, P.eW, 0);
    for (int c = 0; c < NCH; c++) {
        cudaStream_t sg = (c & 1) ? P.s2 : s0;
        cudaStreamWaitEvent(sg, P.ePX[c], 0);
        gemm_mma<K1><<<dim3(4, CH), 256, GSMEM, sg>>>(xc, w1c, b1, curc, c * CH);
        cudaEventRecord(P.eG1[c], sg);
    }

    // s1: scan1 chunks (state chain via s1 stream order)
    for (int c = 0; c < NCH; c++) {
        cudaStreamWaitEvent(P.s1, P.eG1[c], 0);
        scan1_kernel<<<dim3(2, B_), 128, 0, P.s1>>>(c * CH);
        cudaEventRecord(P.eS1[c], P.s1);
    }

    // gemm2 chunks: even -> s2, odd -> s0 (opposite parity; slots behind late g1 chunks)
    for (int c = 0; c < NCH; c++) {
        cudaStream_t sg = (c & 1) ? s0 : P.s2;
        cudaStreamWaitEvent(sg, P.eS1[c], 0);
        gemm_mma<K2><<<dim3(4, CH), 256, GSMEM, sg>>>(s1c, w2c, b2, curc, c * CH);
        cudaEventRecord(P.eG2[c], sg);
    }

    // s3: scan2 chunks (state chain via s3 stream order)
    for (int c = 0; c < NCH; c++) {
        cudaStreamWaitEvent(P.s3, P.eG2[c], 0);
        scan2_kernel<<<dim3(2, B_), 128, 0, P.s3>>>(c * CH);
    }
    cudaEventRecord(P.eFin, P.s3);

    // ---- JOIN: every forked stream merges back into s0 before capture ends ----
    cudaStreamWaitEvent(s0, P.eS1[NCH - 1], 0);   // joins s1
    cudaStreamWaitEvent(s0, P.eG2[NCH - 1], 0);   // joins s2 (c4 even -> s2)
    cudaStreamWaitEvent(s0, P.eFin, 0);           // joins s3
    final_kernel<<<B_, 128, 0, s0>>>(W3, b3, out);
}